// round 3
// baseline (speedup 1.0000x reference)
#include <cuda_runtime.h>

// Problem constants
#define N_EDGES_C   1600000
#define NF4_C       40             // 160 features / 4

// Math constants (computed in double precision, rounded to float)
__device__ __constant__ float kAlpha        = 0.8333333333333333f;       // 5/6
__device__ __constant__ float kStart        = 0.002478752180236578f;     // exp(-6)
__device__ __constant__ float kDeltaM       = 0.007854498012624675f;     // (1-exp(-6))/127
__device__ __constant__ float kBeta         = 4116.381303698453f;        // ((2/128)*(1-exp(-6)))^-2
__device__ __constant__ float kGDelta       = 0.3225806451612903f;       // 10/31
__device__ __constant__ float kGInv         = 20.48f;                    // 1/(2*w^2), w=0.15625
__device__ __constant__ float kPiOverCutoff = 0.5235987755982988f;       // pi/6
__device__ __constant__ float kCutoff       = 6.0f;

__global__ __launch_bounds__(256)
void edge_feature_kernel(const float* __restrict__ pos,
                         const int* __restrict__ edge_index,
                         float* __restrict__ out)
{
    __shared__ float s_d[256];   // distance
    __shared__ float s_c[256];   // cosine cutoff
    __shared__ float s_e[256];   // exp(-alpha*d)

    const int t = threadIdx.x;
    const long long ebase = (long long)blockIdx.x * 256;

    // ---------------- Phase 1: per-edge scalars (accurate math, once/edge) ----
    {
        const long long e = ebase + t;
        const int s = edge_index[e];
        const int d = edge_index[N_EDGES_C + e];

        const float sx = __ldg(&pos[3 * s + 0]);
        const float sy = __ldg(&pos[3 * s + 1]);
        const float sz = __ldg(&pos[3 * s + 2]);
        const float dx = sx - __ldg(&pos[3 * d + 0]);
        const float dy = sy - __ldg(&pos[3 * d + 1]);
        const float dz = sz - __ldg(&pos[3 * d + 2]);

        const float dist = sqrtf(fmaf(dx, dx, fmaf(dy, dy, fmaf(dz, dz, 1e-12f))));
        float c = 0.5f * (cosf(dist * kPiOverCutoff) + 1.0f);
        c = (dist < kCutoff) ? c : 0.0f;

        s_d[t] = dist;
        s_c[t] = c;
        s_e[t] = expf(-kAlpha * dist);   // accurate: error here is amplified by 2*beta*u
    }
    __syncthreads();

    // ---------------- Phase 2: write features, one float4 per thread per iter ----
    // Global float4 index for thread t at iteration k:  ebase*40 + k*256 + t
    float4* __restrict__ out4 = reinterpret_cast<float4*>(out) + ebase * NF4_C;

    #pragma unroll 5
    for (int k = 0; k < NF4_C; ++k) {
        const unsigned q  = (unsigned)(k * 256 + t);
        const unsigned le = q / NF4_C;          // local edge in tile
        const unsigned f4 = q - le * NF4_C;     // float4 slot 0..39

        const float dist = s_d[le];
        const float c    = s_c[le];
        const float ex   = s_e[le];

        float4 v;
        if (f4 < 32u) {
            // exp-normal smearing, features j = 4*f4 .. 4*f4+3
            float m = fmaf((float)(4u * f4), kDeltaM, kStart);
            float u;
            u = ex - m; v.x = c * __expf(-kBeta * u * u); m += kDeltaM;
            u = ex - m; v.y = c * __expf(-kBeta * u * u); m += kDeltaM;
            u = ex - m; v.z = c * __expf(-kBeta * u * u); m += kDeltaM;
            u = ex - m; v.w = c * __expf(-kBeta * u * u);
        } else {
            // gaussian expansion, features j = 4*(f4-32) .. +3
            float cc = (float)(4u * (f4 - 32u)) * kGDelta;
            float u;
            u = dist - cc; v.x = __expf(-u * u * kGInv); cc += kGDelta;
            u = dist - cc; v.y = __expf(-u * u * kGInv); cc += kGDelta;
            u = dist - cc; v.z = __expf(-u * u * kGInv); cc += kGDelta;
            u = dist - cc; v.w = __expf(-u * u * kGInv);
        }
        out4[q] = v;
    }
}

extern "C" void kernel_launch(void* const* d_in, const int* in_sizes, int n_in,
                              void* d_out, int out_size)
{
    const float* pos = (const float*)d_in[0];
    const int*   ei  = (const int*)d_in[1];
    float*       out = (float*)d_out;

    // 1,600,000 edges / 256 per block = 6250 blocks exactly
    edge_feature_kernel<<<N_EDGES_C / 256, 256>>>(pos, ei, out);
}

// round 6
// speedup vs baseline: 1.1354x; 1.1354x over previous
#include <cuda_runtime.h>
#include <math.h>

#define N_EDGES_C   1600000

// ---------------------------------------------------------------------------
// Phase 1 constants (accurate path, once per edge)
__device__ __constant__ float kPiOverCutoff = 0.5235987755982988f;   // pi/6
__device__ __constant__ float kCutoff       = 6.0f;

__global__ __launch_bounds__(256)
void edge_feature_kernel(const float* __restrict__ pos,
                         const int* __restrict__ edge_index,
                         float* __restrict__ out,
                         // exp-normal RBF constants (host-computed in double)
                         float cAlpha,   // 5/6
                         float cStart,   // exp(-6)
                         float cDelta,   // (1-exp(-6))/127
                         float cBeta,    // ((2/128)(1-exp(-6)))^-2
                         float cTwoBD,   // 2*beta*delta
                         float cNegBD2,  // -beta*delta^2
                         float cQE,      // exp(-2*beta*delta^2)
                         // gaussian constants
                         float cGDelta,  // 10/31
                         float cGInv,    // 20.48
                         float cTwoGD,   // 2*gInv*gDelta
                         float cNegGD2,  // -gInv*gDelta^2
                         float cQG)      // exp(-2*gInv*gDelta^2)
{
    __shared__ float s_d[256];   // distance
    __shared__ float s_c[256];   // cosine cutoff
    __shared__ float s_e[256];   // exp(-alpha*d)

    const int t = threadIdx.x;
    const long long ebase = (long long)blockIdx.x * 256;

    // ---------------- Phase 1: per-edge scalars (accurate, once per edge) ----
    {
        const long long e = ebase + t;
        const int s = edge_index[e];
        const int d = edge_index[N_EDGES_C + e];

        const float sx = __ldg(&pos[3 * s + 0]);
        const float sy = __ldg(&pos[3 * s + 1]);
        const float sz = __ldg(&pos[3 * s + 2]);
        const float dx = sx - __ldg(&pos[3 * d + 0]);
        const float dy = sy - __ldg(&pos[3 * d + 1]);
        const float dz = sz - __ldg(&pos[3 * d + 2]);

        const float dist = sqrtf(fmaf(dx, dx, fmaf(dy, dy, fmaf(dz, dz, 1e-12f))));
        float c = 0.5f * (cosf(dist * kPiOverCutoff) + 1.0f);
        c = (dist < kCutoff) ? c : 0.0f;

        s_d[t] = dist;
        s_c[t] = c;
        s_e[t] = expf(-cAlpha * dist);   // accurate: error amplified by 2*beta*u
    }
    __syncthreads();

    // ---------------- Phase 2: 8 threads per edge, geometric recurrence ------
    const int sub  = t & 7;     // which float4 column set this thread owns
    const int lrow = t >> 3;    // edge-within-32 group

    const float fsub = (float)sub;
    // exp-normal means at feature index 4*(sub+8j):  m_j = start + (4*sub + 32*j)*delta
    const float m0 = fmaf(fsub, 4.0f * cDelta, cStart);
    const float m1 = fmaf(32.0f, cDelta, m0);
    const float m2 = fmaf(64.0f, cDelta, m0);
    const float m3 = fmaf(96.0f, cDelta, m0);
    // gaussian center at feature 4*sub
    const float gc0 = fsub * (4.0f * cGDelta);

    const float qE2 = cQE;  // ratio-of-ratios
    const float qG2 = cQG;

    float4* __restrict__ o4 = reinterpret_cast<float4*>(out)
                              + ebase * 40 + (long long)lrow * 40 + sub;

    #pragma unroll 1
    for (int tile = 0; tile < 8; ++tile) {
        const int le = tile * 32 + lrow;
        const float dist = s_d[le];
        const float cut  = s_c[le];
        const float ex   = s_e[le];

        // j = 0..3 : exp-normal groups (f4 = sub + 8j)
        {
            float u, f0, r;
            float4 v;

            u  = ex - m0;
            f0 = cut * __expf(-cBeta * (u * u));
            r  = __expf(fmaf(cTwoBD, u, cNegBD2));
            v.x = f0; v.y = f0 * r; r *= qE2; v.z = v.y * r; r *= qE2; v.w = v.z * r;
            __stcs(&o4[0], v);

            u  = ex - m1;
            f0 = cut * __expf(-cBeta * (u * u));
            r  = __expf(fmaf(cTwoBD, u, cNegBD2));
            v.x = f0; v.y = f0 * r; r *= qE2; v.z = v.y * r; r *= qE2; v.w = v.z * r;
            __stcs(&o4[8], v);

            u  = ex - m2;
            f0 = cut * __expf(-cBeta * (u * u));
            r  = __expf(fmaf(cTwoBD, u, cNegBD2));
            v.x = f0; v.y = f0 * r; r *= qE2; v.z = v.y * r; r *= qE2; v.w = v.z * r;
            __stcs(&o4[16], v);

            u  = ex - m3;
            f0 = cut * __expf(-cBeta * (u * u));
            r  = __expf(fmaf(cTwoBD, u, cNegBD2));
            v.x = f0; v.y = f0 * r; r *= qE2; v.z = v.y * r; r *= qE2; v.w = v.z * r;
            __stcs(&o4[24], v);
        }

        // j = 4 : gaussian group (f4 = 32 + sub), centers (4*sub + i)*gDelta
        {
            const float u  = dist - gc0;
            const float f0 = __expf(-cGInv * (u * u));
            // ratio argument can reach ~130 for large dist -> clamp (exact: the
            // whole group is a true zero whenever the clamp engages)
            float a = fmaf(cTwoGD, u, cNegGD2);
            a = fminf(a, 85.0f);
            float r = __expf(a);
            float4 v;
            v.x = f0; v.y = f0 * r; r *= qG2; v.z = v.y * r; r *= qG2; v.w = v.z * r;
            __stcs(&o4[32], v);
        }

        o4 += 32 * 40;
    }
}

extern "C" void kernel_launch(void* const* d_in, const int* in_sizes, int n_in,
                              void* d_out, int out_size)
{
    const float* pos = (const float*)d_in[0];
    const int*   ei  = (const int*)d_in[1];
    float*       out = (float*)d_out;

    // Host-side double-precision constant computation
    const double cutoff = 6.0;
    const double alpha  = 5.0 / cutoff;
    const double start  = exp(-cutoff);
    const double delta  = (1.0 - start) / 127.0;           // NUM_RBF-1
    const double betaD  = pow((2.0 / 128.0) * (1.0 - start), -2.0);
    const double twoBD  = 2.0 * betaD * delta;
    const double negBD2 = -betaD * delta * delta;
    const double qE     = exp(-2.0 * betaD * delta * delta);

    const double gDelta = 10.0 / 31.0;                      // GAUSS span / (NB-1)
    const double gW     = 0.5 * 10.0 / 32.0;                // width
    const double gInv   = 1.0 / (2.0 * gW * gW);            // 20.48
    const double twoGD  = 2.0 * gInv * gDelta;
    const double negGD2 = -gInv * gDelta * gDelta;
    const double qG     = exp(-2.0 * gInv * gDelta * gDelta);

    edge_feature_kernel<<<N_EDGES_C / 256, 256>>>(
        pos, ei, out,
        (float)alpha, (float)start, (float)delta, (float)betaD,
        (float)twoBD, (float)negBD2, (float)qE,
        (float)gDelta, (float)gInv, (float)twoGD, (float)negGD2, (float)qG);
}

// round 7
// speedup vs baseline: 1.1482x; 1.0113x over previous
#include <cuda_runtime.h>
#include <math.h>

#define N_EDGES_C   1600000

__device__ __constant__ float kPiOverCutoff = 0.5235987755982988f;   // pi/6
__device__ __constant__ float kCutoff       = 6.0f;

__global__ __launch_bounds__(256)
void edge_feature_kernel(const float* __restrict__ pos,
                         const int* __restrict__ edge_index,
                         float* __restrict__ out,
                         // exp-normal RBF constants (host-computed in double)
                         float cAlpha,   // 5/6
                         float cStart,   // exp(-6)
                         float cDelta,   // (1-exp(-6))/127
                         float cBeta,    // ((2/128)(1-exp(-6)))^-2
                         float cTwoBD,   // 2*beta*delta
                         float cNegBD2,  // -beta*delta^2
                         float cQE,      // exp(-2*beta*delta^2)
                         // gaussian constants
                         float cGDelta,  // 10/31
                         float cGInv,    // 20.48
                         float cTwoGD,   // 2*gInv*gDelta
                         float cNegGD2,  // -gInv*gDelta^2
                         float cQG)      // exp(-2*gInv*gDelta^2)
{
    const int t    = threadIdx.x;
    const int lane = t & 31;
    const int warp = t >> 5;

    // First edge owned by this warp (32 edges per warp, 8 warps per block)
    const long long wbase = (long long)blockIdx.x * 256 + warp * 32;

    // ---------------- Phase 1: per-edge scalars, one edge per lane (registers,
    // no smem, no block barrier — warps fully independent) --------------------
    float r_d, r_c, r_e;
    {
        const long long e = wbase + lane;
        const int s = edge_index[e];
        const int d = edge_index[N_EDGES_C + e];

        const float sx = __ldg(&pos[3 * s + 0]);
        const float sy = __ldg(&pos[3 * s + 1]);
        const float sz = __ldg(&pos[3 * s + 2]);
        const float dx = sx - __ldg(&pos[3 * d + 0]);
        const float dy = sy - __ldg(&pos[3 * d + 1]);
        const float dz = sz - __ldg(&pos[3 * d + 2]);

        const float dist = sqrtf(fmaf(dx, dx, fmaf(dy, dy, fmaf(dz, dz, 1e-12f))));
        float c = 0.5f * (cosf(dist * kPiOverCutoff) + 1.0f);
        c = (dist < kCutoff) ? c : 0.0f;

        r_d = dist;
        r_c = c;
        r_e = expf(-cAlpha * dist);   // accurate: error amplified by 2*beta*u
    }

    // ---------------- Phase 2: 8 threads per edge, 4 edges per warp-tile -----
    const int sub  = lane & 7;     // float4 column set this thread owns
    const int erow = lane >> 3;    // edge-within-tile (0..3)

    const float fsub = (float)sub;
    // exp-normal means at feature index 4*(sub+8j): m_j = start + (4*sub + 32*j)*delta
    const float m0 = fmaf(fsub, 4.0f * cDelta, cStart);
    const float m1 = fmaf(32.0f, cDelta, m0);
    const float m2 = fmaf(64.0f, cDelta, m0);
    const float m3 = fmaf(96.0f, cDelta, m0);
    // gaussian center at feature 4*sub
    const float gc0 = fsub * (4.0f * cGDelta);

    const float qE2 = cQE;
    const float qG2 = cQG;

    float4* __restrict__ o4 = reinterpret_cast<float4*>(out)
                              + (wbase + erow) * 40 + sub;

    #pragma unroll 1
    for (int tile = 0; tile < 8; ++tile) {
        const int src = tile * 4 + erow;   // lane holding this edge's scalars
        const float dist = __shfl_sync(0xffffffffu, r_d, src);
        const float cut  = __shfl_sync(0xffffffffu, r_c, src);
        const float ex   = __shfl_sync(0xffffffffu, r_e, src);

        // j = 0..3 : exp-normal groups (f4 = sub + 8j), geometric 4-chain
        {
            float u, f0, r;
            float4 v;

            u  = ex - m0;
            f0 = cut * __expf(-cBeta * (u * u));
            r  = __expf(fmaf(cTwoBD, u, cNegBD2));
            v.x = f0; v.y = f0 * r; r *= qE2; v.z = v.y * r; r *= qE2; v.w = v.z * r;
            __stcs(&o4[0], v);

            u  = ex - m1;
            f0 = cut * __expf(-cBeta * (u * u));
            r  = __expf(fmaf(cTwoBD, u, cNegBD2));
            v.x = f0; v.y = f0 * r; r *= qE2; v.z = v.y * r; r *= qE2; v.w = v.z * r;
            __stcs(&o4[8], v);

            u  = ex - m2;
            f0 = cut * __expf(-cBeta * (u * u));
            r  = __expf(fmaf(cTwoBD, u, cNegBD2));
            v.x = f0; v.y = f0 * r; r *= qE2; v.z = v.y * r; r *= qE2; v.w = v.z * r;
            __stcs(&o4[16], v);

            u  = ex - m3;
            f0 = cut * __expf(-cBeta * (u * u));
            r  = __expf(fmaf(cTwoBD, u, cNegBD2));
            v.x = f0; v.y = f0 * r; r *= qE2; v.z = v.y * r; r *= qE2; v.w = v.z * r;
            __stcs(&o4[24], v);
        }

        // j = 4 : gaussian group (f4 = 32 + sub), centers (4*sub + i)*gDelta
        {
            const float u  = dist - gc0;
            const float f0 = __expf(-cGInv * (u * u));
            // ratio argument can reach ~130 for large dist -> clamp (exact: the
            // whole group is a true zero whenever the clamp engages)
            float a = fmaf(cTwoGD, u, cNegGD2);
            a = fminf(a, 85.0f);
            float r = __expf(a);
            float4 v;
            v.x = f0; v.y = f0 * r; r *= qG2; v.z = v.y * r; r *= qG2; v.w = v.z * r;
            __stcs(&o4[32], v);
        }

        o4 += 4 * 40;   // next 4 edges
    }
}

extern "C" void kernel_launch(void* const* d_in, const int* in_sizes, int n_in,
                              void* d_out, int out_size)
{
    const float* pos = (const float*)d_in[0];
    const int*   ei  = (const int*)d_in[1];
    float*       out = (float*)d_out;

    // Host-side double-precision constant computation
    const double cutoff = 6.0;
    const double alpha  = 5.0 / cutoff;
    const double start  = exp(-cutoff);
    const double delta  = (1.0 - start) / 127.0;           // NUM_RBF-1
    const double betaD  = pow((2.0 / 128.0) * (1.0 - start), -2.0);
    const double twoBD  = 2.0 * betaD * delta;
    const double negBD2 = -betaD * delta * delta;
    const double qE     = exp(-2.0 * betaD * delta * delta);

    const double gDelta = 10.0 / 31.0;                      // GAUSS span / (NB-1)
    const double gW     = 0.5 * 10.0 / 32.0;                // width
    const double gInv   = 1.0 / (2.0 * gW * gW);            // 20.48
    const double twoGD  = 2.0 * gInv * gDelta;
    const double negGD2 = -gInv * gDelta * gDelta;
    const double qG     = exp(-2.0 * gInv * gDelta * gDelta);

    edge_feature_kernel<<<N_EDGES_C / 256, 256>>>(
        pos, ei, out,
        (float)alpha, (float)start, (float)delta, (float)betaD,
        (float)twoBD, (float)negBD2, (float)qE,
        (float)gDelta, (float)gInv, (float)twoGD, (float)negGD2, (float)qG);
}